// round 2
// baseline (speedup 1.0000x reference)
#include <cuda_runtime.h>
#include <math.h>

#define NN      50000
#define IN_F    256
#define HID     128
#define HEADS   4
#define EE      800000
#define COLS    (HEADS * HID)          // 512
#define ALPHA_L 0.2f
#define INV_SCALE 0.04419417382415922f // 1/sqrt(512)
#define LN_EPS  1e-6f

// ---------------- scratch (static device memory; no allocations) ------------
__device__ float  g_X[(size_t)NN * COLS];   // 102.4 MB: per-head projected features
__device__ float  g_s1[NN * HEADS];
__device__ float  g_s2[NN * HEADS];
__device__ float4 g_es[EE];                 // per-edge scores (4 heads), CSR order
__device__ int    g_dsts[EE];               // dst per edge, CSR order
__device__ int    g_deg[NN];
__device__ int    g_rowptr[NN + 1];
__device__ int    g_cursor[NN];
__device__ int    g_is64;                   // edge dtype flag

// ---------------- helpers ---------------------------------------------------
__device__ __forceinline__ int load_edge(const void* e, long long idx) {
    if (g_is64) return (int)((const long long*)e)[idx];
    return ((const int*)e)[idx];
}

__device__ __forceinline__ void fma2(unsigned long long& acc,
                                     unsigned long long a,
                                     unsigned long long b) {
    asm("fma.rn.f32x2 %0, %1, %2, %0;" : "+l"(acc) : "l"(a), "l"(b));
}

__device__ __forceinline__ float ull_lo(unsigned long long v) {
    return __uint_as_float((unsigned)v);
}
__device__ __forceinline__ float ull_hi(unsigned long long v) {
    return __uint_as_float((unsigned)(v >> 32));
}

// ---------------- kernels ---------------------------------------------------
__global__ void zero_deg_kernel() {
    int i = blockIdx.x * blockDim.x + threadIdx.x;
    if (i < NN) g_deg[i] = 0;
}

// Detect int64 vs int32 edge buffer: for int64 (values < 2^31, nonneg) every
// odd 32-bit word is zero; for int32 those words are random node ids.
__global__ void detect_kernel(const int* __restrict__ edge_raw) {
    int lane = threadIdx.x & 31;
    int bad = 0;
    for (int i = lane; i < 2048; i += 32)
        if (edge_raw[2 * i + 1] != 0) bad = 1;
    unsigned m = __ballot_sync(0xffffffffu, bad);
    if (lane == 0 && blockIdx.x == 0) g_is64 = (m == 0);
}

// Tiled fp32 GEMM with packed f32x2 FMA (Blackwell FFMA2):
// X[n, h*128+c] = sum_k emb[n,k] * W[h,c,k] + b[h,c]
// BM=BN=128, BK=16, 256 threads, 8x8 micro-tile; A tile stored DUPLICATED
// ([a,a] pairs) so the packed multiplier loads as one LDS.64/.128 broadcast.
// Epilogue also computes s1 = x.a1, s2 = x.a2 (16-lane reduction) so the
// standalone s_kernel is gone.
__global__ __launch_bounds__(256) void gemm_kernel(
    const float* __restrict__ emb, const float* __restrict__ W,
    const float* __restrict__ bias, const float* __restrict__ a_attn)
{
    __shared__ float As2[16][256];   // duplicated A: As2[k][2r]=As2[k][2r+1]=A[r][k]
    __shared__ float Bs[16][128];
    const int h   = blockIdx.y;
    const int bm  = blockIdx.x * 128;
    const int tid = threadIdx.x;
    const int tx  = tid & 15, ty = tid >> 4;
    const float* Wh = W + (size_t)h * HID * IN_F;

    unsigned long long acc2[8][4];
#pragma unroll
    for (int i = 0; i < 8; i++)
#pragma unroll
        for (int j = 0; j < 4; j++) acc2[i][j] = 0ull;

    for (int k0 = 0; k0 < IN_F; k0 += 16) {
        // A tile: 128 rows x 16 k (512 float4, 2 per thread), row 0 => zeros
#pragma unroll
        for (int l = 0; l < 2; l++) {
            int idx = tid * 2 + l;            // 0..511
            int row = idx >> 2;
            int c4  = (idx & 3) * 4;
            int grow = bm + row;
            float4 v = make_float4(0.f, 0.f, 0.f, 0.f);
            if (grow < NN && grow != 0)
                v = *reinterpret_cast<const float4*>(emb + (size_t)grow * IN_F + k0 + c4);
            *reinterpret_cast<float2*>(&As2[c4 + 0][2 * row]) = make_float2(v.x, v.x);
            *reinterpret_cast<float2*>(&As2[c4 + 1][2 * row]) = make_float2(v.y, v.y);
            *reinterpret_cast<float2*>(&As2[c4 + 2][2 * row]) = make_float2(v.z, v.z);
            *reinterpret_cast<float2*>(&As2[c4 + 3][2 * row]) = make_float2(v.w, v.w);
        }
        // B tile: 128 cols x 16 k from W[h][col][k]
#pragma unroll
        for (int l = 0; l < 2; l++) {
            int idx = tid * 2 + l;
            int col = idx >> 2;
            int c4  = (idx & 3) * 4;
            float4 v = *reinterpret_cast<const float4*>(Wh + (size_t)col * IN_F + k0 + c4);
            Bs[c4 + 0][col] = v.x; Bs[c4 + 1][col] = v.y;
            Bs[c4 + 2][col] = v.z; Bs[c4 + 3][col] = v.w;
        }
        __syncthreads();
#pragma unroll
        for (int kk = 0; kk < 16; kk++) {
            // a-dup pairs for rows ty*8..ty*8+7: contiguous, 64B-aligned
            const ulonglong2* ap =
                reinterpret_cast<const ulonglong2*>(&As2[kk][ty * 16]);
            const ulonglong2* bp =
                reinterpret_cast<const ulonglong2*>(&Bs[kk][tx * 8]);
            ulonglong2 a01 = ap[0], a23 = ap[1], a45 = ap[2], a67 = ap[3];
            ulonglong2 b03 = bp[0], b47 = bp[1];
            unsigned long long ad[8] = {a01.x, a01.y, a23.x, a23.y,
                                        a45.x, a45.y, a67.x, a67.y};
            unsigned long long bd[4] = {b03.x, b03.y, b47.x, b47.y};
#pragma unroll
            for (int i = 0; i < 8; i++)
#pragma unroll
                for (int j = 0; j < 4; j++)
                    fma2(acc2[i][j], ad[i], bd[j]);
        }
        __syncthreads();
    }

    // Epilogue: add bias, store X, and fused s1/s2 projections.
    const float* a1 = a_attn + h * 2 * HID;
    const float* a2 = a1 + HID;
    float bv[8], a1v[8], a2v[8];
#pragma unroll
    for (int j = 0; j < 8; j++) {
        int c = tx * 8 + j;
        bv[j]  = bias[h * HID + c];
        a1v[j] = a1[c];
        a2v[j] = a2[c];
    }
#pragma unroll
    for (int i = 0; i < 8; i++) {
        int grow = bm + ty * 8 + i;
        float x[8];
#pragma unroll
        for (int j = 0; j < 4; j++) {
            x[2 * j]     = ull_lo(acc2[i][j]) + bv[2 * j];
            x[2 * j + 1] = ull_hi(acc2[i][j]) + bv[2 * j + 1];
        }
        float p1 = 0.f, p2 = 0.f;
        if (grow < NN) {
            float* orow = g_X + (size_t)grow * COLS + h * HID + tx * 8;
#pragma unroll
            for (int j = 0; j < 8; j++) {
                orow[j] = x[j];
                p1 = fmaf(x[j], a1v[j], p1);
                p2 = fmaf(x[j], a2v[j], p2);
            }
        }
#pragma unroll
        for (int o = 8; o; o >>= 1) {  // reduce across 16 tx lanes
            p1 += __shfl_xor_sync(0xffffffffu, p1, o);
            p2 += __shfl_xor_sync(0xffffffffu, p2, o);
        }
        if (tx == 0 && grow < NN) {
            g_s1[grow * 4 + h] = p1;
            g_s2[grow * 4 + h] = p2;
        }
    }
}

__global__ void hist_kernel(const void* __restrict__ edge) {
    int e = blockIdx.x * blockDim.x + threadIdx.x;
    if (e >= EE) return;
    int src = load_edge(edge, e);
    atomicAdd(&g_deg[src], 1);
}

// Single-block exclusive scan over 50000 degrees -> rowptr + cursor.
__global__ __launch_bounds__(256) void scan_kernel() {
    __shared__ int sums[256];
    const int t  = threadIdx.x;
    const int CH = (NN + 255) / 256;       // 196
    int beg = t * CH, end = min(beg + CH, NN);
    int s = 0;
    for (int i = beg; i < end; i++) s += g_deg[i];
    sums[t] = s;
    __syncthreads();
    if (t == 0) {
        int run = 0;
        for (int i = 0; i < 256; i++) { int v = sums[i]; sums[i] = run; run += v; }
    }
    __syncthreads();
    int run = sums[t];
    for (int i = beg; i < end; i++) {
        g_rowptr[i] = run;
        g_cursor[i] = run;
        run += g_deg[i];
    }
    if (t == 0) g_rowptr[NN] = EE;
}

// Per-edge: scores for 4 heads + scatter into CSR slots.
__global__ __launch_bounds__(256) void score_scatter_kernel(const void* __restrict__ edge) {
    int e = blockIdx.x * blockDim.x + threadIdx.x;
    if (e >= EE) return;
    int src = load_edge(edge, e);
    int dst = load_edge(edge, (long long)EE + e);
    float4 v1 = *reinterpret_cast<const float4*>(g_s1 + src * 4);
    float4 v2 = *reinterpret_cast<const float4*>(g_s2 + dst * 4);
    float4 sc;
    {
        float s0 = v1.x + v2.x, s1 = v1.y + v2.y, s2 = v1.z + v2.z, s3 = v1.w + v2.w;
        s0 = (s0 >= 0.f ? s0 : ALPHA_L * s0) * INV_SCALE;
        s1 = (s1 >= 0.f ? s1 : ALPHA_L * s1) * INV_SCALE;
        s2 = (s2 >= 0.f ? s2 : ALPHA_L * s2) * INV_SCALE;
        s3 = (s3 >= 0.f ? s3 : ALPHA_L * s3) * INV_SCALE;
        sc = make_float4(expf(s0), expf(s1), expf(s2), expf(s3));
    }
    int pos = atomicAdd(&g_cursor[src], 1);
    g_dsts[pos] = dst;
    g_es[pos]   = sc;
}

// One block (128 thr) per node: gather-aggregate + softmax denom + LayerNorm + ELU.
__global__ __launch_bounds__(128) void agg_ln_kernel(
    const float* __restrict__ gain, const float* __restrict__ beta,
    float* __restrict__ out)
{
    const int n = blockIdx.x;
    const int t = threadIdx.x;
    const int beg = g_rowptr[n], end = g_rowptr[n + 1];

    float a0 = 0.f, a1 = 0.f, a2 = 0.f, a3 = 0.f;
    float r0 = 0.f, r1 = 0.f, r2 = 0.f, r3 = 0.f;
    for (int i = beg; i < end; i++) {
        int d = g_dsts[i];
        float4 e = g_es[i];
        const float* xr = g_X + (size_t)d * COLS;
        a0 = fmaf(e.x, xr[t],            a0);
        a1 = fmaf(e.y, xr[HID + t],      a1);
        a2 = fmaf(e.z, xr[2 * HID + t],  a2);
        a3 = fmaf(e.w, xr[3 * HID + t],  a3);
        r0 += e.x; r1 += e.y; r2 += e.z; r3 += e.w;
    }
    float h0 = a0 / (r0 == 0.f ? 1.f : r0);
    float h1 = a1 / (r1 == 0.f ? 1.f : r1);
    float h2 = a2 / (r2 == 0.f ? 1.f : r2);
    float h3 = a3 / (r3 == 0.f ? 1.f : r3);

    float s  = h0 + h1 + h2 + h3;
    float ss = h0 * h0 + h1 * h1 + h2 * h2 + h3 * h3;
#pragma unroll
    for (int o = 16; o; o >>= 1) {
        s  += __shfl_xor_sync(0xffffffffu, s, o);
        ss += __shfl_xor_sync(0xffffffffu, ss, o);
    }
    __shared__ float rs[4], rss[4];
    int w = t >> 5;
    if ((t & 31) == 0) { rs[w] = s; rss[w] = ss; }
    __syncthreads();
    s  = rs[0] + rs[1] + rs[2] + rs[3];
    ss = rss[0] + rss[1] + rss[2] + rss[3];

    float mean = s * (1.f / 512.f);
    float var  = fmaxf((ss - 512.f * mean * mean) * (1.f / 511.f), 0.f);
    float inv  = 1.f / (sqrtf(var) + LN_EPS);

    float* orow = out + (size_t)n * COLS;
    float hv[4] = {h0, h1, h2, h3};
#pragma unroll
    for (int h = 0; h < 4; h++) {
        int c = h * HID + t;
        float v = gain[c] * (hv[h] - mean) * inv + beta[c];
        orow[c] = v > 0.f ? v : expm1f(v);
    }
}

// ---------------- launch -----------------------------------------------------
extern "C" void kernel_launch(void* const* d_in, const int* in_sizes, int n_in,
                              void* d_out, int out_size)
{
    (void)in_sizes; (void)n_in; (void)out_size;
    // metadata order: data, edge, embed_table, W, b, a_attn, ln_gain, ln_bias
    const void*  edge   = d_in[1];
    const float* emb    = (const float*)d_in[2];
    const float* W      = (const float*)d_in[3];
    const float* bias   = (const float*)d_in[4];
    const float* a_attn = (const float*)d_in[5];
    const float* gain   = (const float*)d_in[6];
    const float* beta   = (const float*)d_in[7];
    float* out = (float*)d_out;

    detect_kernel<<<1, 32>>>((const int*)edge);
    zero_deg_kernel<<<(NN + 255) / 256, 256>>>();

    dim3 gg((NN + 127) / 128, HEADS);
    gemm_kernel<<<gg, 256>>>(emb, W, bias, a_attn);

    hist_kernel<<<(EE + 255) / 256, 256>>>(edge);
    scan_kernel<<<1, 256>>>();
    score_scatter_kernel<<<(EE + 255) / 256, 256>>>(edge);

    agg_ln_kernel<<<NN, 128>>>(gain, beta, out);
}

// round 5
// speedup vs baseline: 2.3814x; 2.3814x over previous
#include <cuda_runtime.h>
#include <cuda_bf16.h>
#include <math.h>
#include <stdint.h>

#define NN      50000
#define IN_F    256
#define HID     128
#define HEADS   4
#define EE      800000
#define COLS    (HEADS * HID)          // 512
#define ALPHA_L 0.2f
#define INV_SCALE 0.04419417382415922f // 1/sqrt(512)
#define LN_EPS  1e-6f

#define M_TILES ((NN + 127) / 128)     // 391
#define M_PAD   (M_TILES * 128)        // 50048

// ---------------- scratch (static device memory; no allocations) ------------
__device__ float          g_X[(size_t)NN * COLS];     // 102.4 MB
__device__ float          g_s1[NN * HEADS];
__device__ float          g_s2[NN * HEADS];
__device__ __nv_bfloat16  g_Ahi[(size_t)M_PAD * IN_F];
__device__ __nv_bfloat16  g_Alo[(size_t)M_PAD * IN_F];
__device__ __nv_bfloat16  g_Bhi[COLS * IN_F];         // W split hi (512x256)
__device__ __nv_bfloat16  g_Blo[COLS * IN_F];
__device__ float4         g_es[EE];
__device__ int            g_dsts[EE];
__device__ int            g_deg[NN];
__device__ int            g_rowptr[NN + 1];
__device__ int            g_cursor[NN];
__device__ int            g_is64;

// ---------------- helpers ---------------------------------------------------
__device__ __forceinline__ int load_edge(const void* e, long long idx) {
    if (g_is64) return (int)((const long long*)e)[idx];
    return ((const int*)e)[idx];
}
__device__ __forceinline__ uint32_t smem_u32(const void* p) {
    uint32_t a;
    asm("{ .reg .u64 t; cvta.to.shared.u64 t, %1; cvt.u32.u64 %0, t; }"
        : "=r"(a) : "l"(p));
    return a;
}
__device__ __forceinline__ void ldsm4(uint32_t* r, uint32_t addr) {
    asm volatile("ldmatrix.sync.aligned.m8n8.x4.shared.b16 {%0,%1,%2,%3}, [%4];"
                 : "=r"(r[0]), "=r"(r[1]), "=r"(r[2]), "=r"(r[3]) : "r"(addr));
}
__device__ __forceinline__ void mma_bf16(float* c, const uint32_t* a,
                                         const uint32_t* b) {
    asm volatile(
        "mma.sync.aligned.m16n8k16.row.col.f32.bf16.bf16.f32 "
        "{%0,%1,%2,%3}, {%4,%5,%6,%7}, {%8,%9}, {%0,%1,%2,%3};"
        : "+f"(c[0]), "+f"(c[1]), "+f"(c[2]), "+f"(c[3])
        : "r"(a[0]), "r"(a[1]), "r"(a[2]), "r"(a[3]), "r"(b[0]), "r"(b[1]));
}
__device__ __forceinline__ uint32_t swz(uint32_t off) {
    return off ^ ((off >> 3) & 0x70);
}
__device__ __forceinline__ uint32_t pack2(__nv_bfloat16 a, __nv_bfloat16 b) {
    return (uint32_t)__bfloat16_as_ushort(a) | ((uint32_t)__bfloat16_as_ushort(b) << 16);
}

// smem layout for gemm (dynamic, exactly 48KB -> no opt-in attribute needed)
#define OFF_A_HI 0
#define OFF_A_LO 16384
#define OFF_B_HI 32768
#define OFF_B_LO 40960
#define SMEM_GEMM 49152

// ---------------- small kernels ---------------------------------------------
__global__ void zero_kernel() {
    int i = blockIdx.x * blockDim.x + threadIdx.x;
    if (i < NN * HEADS) { g_s1[i] = 0.f; g_s2[i] = 0.f; }
    if (i < NN) g_deg[i] = 0;
}

__global__ void detect_kernel(const int* __restrict__ edge_raw) {
    int lane = threadIdx.x & 31;
    int bad = 0;
    for (int i = lane; i < 2048; i += 32)
        if (edge_raw[2 * i + 1] != 0) bad = 1;
    unsigned m = __ballot_sync(0xffffffffu, bad);
    if (lane == 0 && blockIdx.x == 0) g_is64 = (m == 0);
}

// Split W (512x256 fp32) into bf16 hi/lo.
__global__ void prep_b_kernel(const float* __restrict__ W) {
    int i = blockIdx.x * blockDim.x + threadIdx.x;
    if (i >= COLS * IN_F) return;
    float w = W[i];
    __nv_bfloat16 hi = __float2bfloat16(w);
    __nv_bfloat16 lo = __float2bfloat16(w - __bfloat162float(hi));
    g_Bhi[i] = hi;
    g_Blo[i] = lo;
}

// Split emb (padding_idx=0 zeroed; rows >= NN zeroed) into bf16 hi/lo.
__global__ void prep_a_kernel(const float* __restrict__ emb) {
    int i = blockIdx.x * blockDim.x + threadIdx.x;   // float4 granularity
    if (i >= M_PAD * (IN_F / 4)) return;
    int row = i >> 6;
    int c4  = i & 63;
    float4 v = make_float4(0.f, 0.f, 0.f, 0.f);
    if (row < NN && row != 0)
        v = *reinterpret_cast<const float4*>(emb + (size_t)row * IN_F + c4 * 4);
    __nv_bfloat16 h0 = __float2bfloat16(v.x), h1 = __float2bfloat16(v.y);
    __nv_bfloat16 h2 = __float2bfloat16(v.z), h3 = __float2bfloat16(v.w);
    __nv_bfloat16 l0 = __float2bfloat16(v.x - __bfloat162float(h0));
    __nv_bfloat16 l1 = __float2bfloat16(v.y - __bfloat162float(h1));
    __nv_bfloat16 l2 = __float2bfloat16(v.z - __bfloat162float(h2));
    __nv_bfloat16 l3 = __float2bfloat16(v.w - __bfloat162float(h3));
    size_t off = (size_t)row * IN_F + c4 * 4;
    *reinterpret_cast<uint2*>(g_Ahi + off) = make_uint2(pack2(h0, h1), pack2(h2, h3));
    *reinterpret_cast<uint2*>(g_Alo + off) = make_uint2(pack2(l0, l1), pack2(l2, l3));
}

// ---------------- split-bf16 HMMA GEMM ---------------------------------------
// grid (391, 8): CTA = rows bm..bm+127, cols by*64..by*64+63.
// 8 warps in 4x2; warp tile 32x32. K in 4 chunks of 64 through swizzled smem.
// D = Ahi Bhi^T + Ahi Blo^T + Alo Bhi^T (split-bf16 ~ fp32 accuracy).
__global__ __launch_bounds__(256, 2) void gemm_mma_kernel(
    const float* __restrict__ bias, const float* __restrict__ a_attn)
{
    extern __shared__ char smem[];
    const uint32_t sb = smem_u32(smem);
    const int tid  = threadIdx.x;
    const int wid  = tid >> 5;
    const int lane = tid & 31;
    const int wm   = wid & 3;        // 0..3 (rows)
    const int wn   = wid >> 2;       // 0..1 (cols)
    const int bm   = blockIdx.x * 128;
    const int bn   = blockIdx.y * 64;
    const int h    = bn >> 7;        // head

    float acc[2][4][4];
#pragma unroll
    for (int i = 0; i < 2; i++)
#pragma unroll
        for (int j = 0; j < 4; j++)
#pragma unroll
            for (int r = 0; r < 4; r++) acc[i][j][r] = 0.f;

    // per-lane ldmatrix address bases (swizzle XOR is row-dependent, k<128B)
    const int arow = wm * 32 + (lane & 15);
    const uint32_t a_kx      = (uint32_t)((arow & 7) << 4);
    const uint32_t a_base_hi = sb + OFF_A_HI + arow * 128;
    const uint32_t a_klane   = (uint32_t)((lane >> 4) << 4);  // 0/16 bytes
    const int m4   = lane >> 3;                               // 8x8 matrix id
    const int brow = wn * 32 + ((m4 >> 1) << 3) + (lane & 7);
    const uint32_t b_kx      = (uint32_t)((brow & 7) << 4);
    const uint32_t b_base_hi = sb + OFF_B_HI + brow * 128;
    const uint32_t b_klane   = (uint32_t)((m4 & 1) << 4);

    for (int kc = 0; kc < 4; kc++) {
        __syncthreads();
        // ---- A chunk: 128 rows x 64 k, hi+lo (1024 uint4 each) ----
#pragma unroll
        for (int l = 0; l < 4; l++) {
            int idx = tid + 256 * l;
            int row = idx >> 3;
            int c16 = idx & 7;
            uint32_t so = swz(row * 128 + c16 * 16);
            size_t asrc = (size_t)(bm + row) * IN_F + kc * 64 + c16 * 8;
            *reinterpret_cast<uint4*>(smem + OFF_A_HI + so) =
                *reinterpret_cast<const uint4*>(g_Ahi + asrc);
            *reinterpret_cast<uint4*>(smem + OFF_A_LO + so) =
                *reinterpret_cast<const uint4*>(g_Alo + asrc);
        }
        // ---- B chunk: 64 rows x 64 k, hi+lo (512 uint4 each) ----
#pragma unroll
        for (int l = 0; l < 2; l++) {
            int idx = tid + 256 * l;
            int row = idx >> 3;
            int c16 = idx & 7;
            uint32_t so = swz(row * 128 + c16 * 16);
            size_t bsrc = (size_t)(bn + row) * IN_F + kc * 64 + c16 * 8;
            *reinterpret_cast<uint4*>(smem + OFF_B_HI + so) =
                *reinterpret_cast<const uint4*>(g_Bhi + bsrc);
            *reinterpret_cast<uint4*>(smem + OFF_B_LO + so) =
                *reinterpret_cast<const uint4*>(g_Blo + bsrc);
        }
        __syncthreads();

        // ---- compute: 4 k-steps of 16 ----
#pragma unroll
        for (int ks = 0; ks < 4; ks++) {
            const uint32_t akb = (uint32_t)(ks * 32) + a_klane;
            const uint32_t bkb = (uint32_t)(ks * 32) + b_klane;
            uint32_t af[2][4], bh[2][4], bl[2][4];
#pragma unroll
            for (int i = 0; i < 2; i++)
                ldsm4(af[i], a_base_hi + i * 2048 + (akb ^ a_kx));
#pragma unroll
            for (int jp = 0; jp < 2; jp++)
                ldsm4(bh[jp], b_base_hi + jp * 2048 + (bkb ^ b_kx));
            // hi*hi
#pragma unroll
            for (int i = 0; i < 2; i++)
#pragma unroll
                for (int j = 0; j < 4; j++)
                    mma_bf16(acc[i][j], af[i], &bh[j >> 1][(j & 1) * 2]);
            // hi*lo
#pragma unroll
            for (int jp = 0; jp < 2; jp++)
                ldsm4(bl[jp], b_base_hi + 8192 + jp * 2048 + (bkb ^ b_kx));
#pragma unroll
            for (int i = 0; i < 2; i++)
#pragma unroll
                for (int j = 0; j < 4; j++)
                    mma_bf16(acc[i][j], af[i], &bl[j >> 1][(j & 1) * 2]);
            // lo*hi (reuse af registers)
#pragma unroll
            for (int i = 0; i < 2; i++)
                ldsm4(af[i], a_base_hi + 16384 + i * 2048 + (akb ^ a_kx));
#pragma unroll
            for (int i = 0; i < 2; i++)
#pragma unroll
                for (int j = 0; j < 4; j++)
                    mma_bf16(acc[i][j], af[i], &bh[j >> 1][(j & 1) * 2]);
        }
    }
    __syncthreads();

    // ---- epilogue: bias + X store + fused s1/s2 partials --------------------
    float* s1b = reinterpret_cast<float*>(smem);          // [128]
    float* s2b = reinterpret_cast<float*>(smem) + 128;    // [128]
    if (tid < 128) { s1b[tid] = 0.f; s2b[tid] = 0.f; }
    __syncthreads();

    const int chbase = bn - h * 128;                      // 0 or 64
    const float* a1 = a_attn + h * 2 * HID + chbase;
    const float* a2 = a1 + HID;
#pragma unroll
    for (int i = 0; i < 2; i++) {
        int r0 = wm * 32 + i * 16 + (lane >> 2);          // local row of (c0,c1)
        float p1a = 0.f, p2a = 0.f, p1b = 0.f, p2b = 0.f;
#pragma unroll
        for (int j = 0; j < 4; j++) {
            int c = wn * 32 + j * 8 + 2 * (lane & 3);     // local col (0..63)
            float b0 = bias[bn + c], b1 = bias[bn + c + 1];
            float x00 = acc[i][j][0] + b0, x01 = acc[i][j][1] + b1;
            float x10 = acc[i][j][2] + b0, x11 = acc[i][j][3] + b1;
            int gr0 = bm + r0, gr1 = gr0 + 8;
            if (gr0 < NN)
                *reinterpret_cast<float2*>(g_X + (size_t)gr0 * COLS + bn + c) =
                    make_float2(x00, x01);
            if (gr1 < NN)
                *reinterpret_cast<float2*>(g_X + (size_t)gr1 * COLS + bn + c) =
                    make_float2(x10, x11);
            float w10 = a1[c], w11 = a1[c + 1], w20 = a2[c], w21 = a2[c + 1];
            p1a = fmaf(x00, w10, fmaf(x01, w11, p1a));
            p2a = fmaf(x00, w20, fmaf(x01, w21, p2a));
            p1b = fmaf(x10, w10, fmaf(x11, w11, p1b));
            p2b = fmaf(x10, w20, fmaf(x11, w21, p2b));
        }
#pragma unroll
        for (int o = 1; o <= 2; o <<= 1) {
            p1a += __shfl_xor_sync(0xffffffffu, p1a, o);
            p2a += __shfl_xor_sync(0xffffffffu, p2a, o);
            p1b += __shfl_xor_sync(0xffffffffu, p1b, o);
            p2b += __shfl_xor_sync(0xffffffffu, p2b, o);
        }
        if ((lane & 3) == 0) {
            atomicAdd(&s1b[r0], p1a);
            atomicAdd(&s2b[r0], p2a);
            atomicAdd(&s1b[r0 + 8], p1b);
            atomicAdd(&s2b[r0 + 8], p2b);
        }
    }
    __syncthreads();
    if (tid < 128 && bm + tid < NN) {
        atomicAdd(&g_s1[(bm + tid) * 4 + h], s1b[tid]);
        atomicAdd(&g_s2[(bm + tid) * 4 + h], s2b[tid]);
    }
}

// ---------------- edge kernels (unchanged, known-good) ----------------------
__global__ void hist_kernel(const void* __restrict__ edge) {
    int e = blockIdx.x * blockDim.x + threadIdx.x;
    if (e >= EE) return;
    int src = load_edge(edge, e);
    atomicAdd(&g_deg[src], 1);
}

__global__ __launch_bounds__(256) void scan_kernel() {
    __shared__ int sums[256];
    const int t  = threadIdx.x;
    const int CH = (NN + 255) / 256;
    int beg = t * CH, end = min(beg + CH, NN);
    int s = 0;
    for (int i = beg; i < end; i++) s += g_deg[i];
    sums[t] = s;
    __syncthreads();
    if (t == 0) {
        int run = 0;
        for (int i = 0; i < 256; i++) { int v = sums[i]; sums[i] = run; run += v; }
    }
    __syncthreads();
    int run = sums[t];
    for (int i = beg; i < end; i++) {
        g_rowptr[i] = run;
        g_cursor[i] = run;
        run += g_deg[i];
    }
    if (t == 0) g_rowptr[NN] = EE;
}

__global__ __launch_bounds__(256) void score_scatter_kernel(const void* __restrict__ edge) {
    int e = blockIdx.x * blockDim.x + threadIdx.x;
    if (e >= EE) return;
    int src = load_edge(edge, e);
    int dst = load_edge(edge, (long long)EE + e);
    float4 v1 = *reinterpret_cast<const float4*>(g_s1 + src * 4);
    float4 v2 = *reinterpret_cast<const float4*>(g_s2 + dst * 4);
    float4 sc;
    {
        float s0 = v1.x + v2.x, s1 = v1.y + v2.y, s2 = v1.z + v2.z, s3 = v1.w + v2.w;
        s0 = (s0 >= 0.f ? s0 : ALPHA_L * s0) * INV_SCALE;
        s1 = (s1 >= 0.f ? s1 : ALPHA_L * s1) * INV_SCALE;
        s2 = (s2 >= 0.f ? s2 : ALPHA_L * s2) * INV_SCALE;
        s3 = (s3 >= 0.f ? s3 : ALPHA_L * s3) * INV_SCALE;
        sc = make_float4(expf(s0), expf(s1), expf(s2), expf(s3));
    }
    int pos = atomicAdd(&g_cursor[src], 1);
    g_dsts[pos] = dst;
    g_es[pos]   = sc;
}

__global__ __launch_bounds__(128) void agg_ln_kernel(
    const float* __restrict__ gain, const float* __restrict__ beta,
    float* __restrict__ out)
{
    const int n = blockIdx.x;
    const int t = threadIdx.x;
    const int beg = g_rowptr[n], end = g_rowptr[n + 1];

    float a0 = 0.f, a1 = 0.f, a2 = 0.f, a3 = 0.f;
    float r0 = 0.f, r1 = 0.f, r2 = 0.f, r3 = 0.f;
    for (int i = beg; i < end; i++) {
        int d = g_dsts[i];
        float4 e = g_es[i];
        const float* xr = g_X + (size_t)d * COLS;
        a0 = fmaf(e.x, xr[t],            a0);
        a1 = fmaf(e.y, xr[HID + t],      a1);
        a2 = fmaf(e.z, xr[2 * HID + t],  a2);
        a3 = fmaf(e.w, xr[3 * HID + t],  a3);
        r0 += e.x; r1 += e.y; r2 += e.z; r3 += e.w;
    }
    float h0 = a0 / (r0 == 0.f ? 1.f : r0);
    float h1 = a1 / (r1 == 0.f ? 1.f : r1);
    float h2 = a2 / (r2 == 0.f ? 1.f : r2);
    float h3 = a3 / (r3 == 0.f ? 1.f : r3);

    float s  = h0 + h1 + h2 + h3;
    float ss = h0 * h0 + h1 * h1 + h2 * h2 + h3 * h3;
#pragma unroll
    for (int o = 16; o; o >>= 1) {
        s  += __shfl_xor_sync(0xffffffffu, s, o);
        ss += __shfl_xor_sync(0xffffffffu, ss, o);
    }
    __shared__ float rs[4], rss[4];
    int w = t >> 5;
    if ((t & 31) == 0) { rs[w] = s; rss[w] = ss; }
    __syncthreads();
    s  = rs[0] + rs[1] + rs[2] + rs[3];
    ss = rss[0] + rss[1] + rss[2] + rss[3];

    float mean = s * (1.f / 512.f);
    float var  = fmaxf((ss - 512.f * mean * mean) * (1.f / 511.f), 0.f);
    float inv  = 1.f / (sqrtf(var) + LN_EPS);

    float* orow = out + (size_t)n * COLS;
    float hv[4] = {h0, h1, h2, h3};
#pragma unroll
    for (int h = 0; h < 4; h++) {
        int c = h * HID + t;
        float v = gain[c] * (hv[h] - mean) * inv + beta[c];
        orow[c] = v > 0.f ? v : expm1f(v);
    }
}

// ---------------- launch -----------------------------------------------------
extern "C" void kernel_launch(void* const* d_in, const int* in_sizes, int n_in,
                              void* d_out, int out_size)
{
    (void)in_sizes; (void)n_in; (void)out_size;
    const void*  edge   = d_in[1];
    const float* emb    = (const float*)d_in[2];
    const float* W      = (const float*)d_in[3];
    const float* bias   = (const float*)d_in[4];
    const float* a_attn = (const float*)d_in[5];
    const float* gain   = (const float*)d_in[6];
    const float* beta   = (const float*)d_in[7];
    float* out = (float*)d_out;

    detect_kernel<<<1, 32>>>((const int*)edge);
    zero_kernel<<<(NN * HEADS + 255) / 256, 256>>>();
    prep_b_kernel<<<(COLS * IN_F + 255) / 256, 256>>>(W);
    prep_a_kernel<<<(M_PAD * (IN_F / 4) + 255) / 256, 256>>>(emb);

    dim3 gg(M_TILES, 8);
    gemm_mma_kernel<<<gg, 256, SMEM_GEMM>>>(bias, a_attn);

    hist_kernel<<<(EE + 255) / 256, 256>>>(edge);
    scan_kernel<<<1, 256>>>();
    score_scatter_kernel<<<(EE + 255) / 256, 256>>>(edge);

    agg_ln_kernel<<<NN, 128>>>(gain, beta, out);
}

// round 6
// speedup vs baseline: 2.7488x; 1.1543x over previous
#include <cuda_runtime.h>
#include <cuda_bf16.h>
#include <math.h>
#include <stdint.h>

#define NN      50000
#define IN_F    256
#define HID     128
#define HEADS   4
#define EE      800000
#define COLS    (HEADS * HID)          // 512
#define ALPHA_L 0.2f
#define INV_SCALE 0.04419417382415922f // 1/sqrt(512)
#define LN_EPS  1e-6f

#define M_TILES ((NN + 127) / 128)     // 391
#define M_PAD   (M_TILES * 128)        // 50048

// ---------------- scratch (static device memory; no allocations) ------------
__device__ float          g_X[(size_t)NN * COLS];     // 102.4 MB
__device__ float          g_s1[NN * HEADS];
__device__ float          g_s2[NN * HEADS];
__device__ __nv_bfloat16  g_Ahi[(size_t)M_PAD * IN_F];
__device__ __nv_bfloat16  g_Alo[(size_t)M_PAD * IN_F];
__device__ __nv_bfloat16  g_Bhi[COLS * IN_F];         // W split hi (512x256)
__device__ __nv_bfloat16  g_Blo[COLS * IN_F];
__device__ float4         g_es[EE];
__device__ int            g_dsts[EE];
__device__ int            g_deg[NN];
__device__ int            g_rowptr[NN + 1];
__device__ int            g_cursor[NN];
__device__ int            g_is64;

// ---------------- helpers ---------------------------------------------------
__device__ __forceinline__ int load_edge(const void* e, long long idx) {
    if (g_is64) return (int)((const long long*)e)[idx];
    return ((const int*)e)[idx];
}
__device__ __forceinline__ uint32_t smem_u32(const void* p) {
    uint32_t a;
    asm("{ .reg .u64 t; cvta.to.shared.u64 t, %1; cvt.u32.u64 %0, t; }"
        : "=r"(a) : "l"(p));
    return a;
}
__device__ __forceinline__ void ldsm4(uint32_t* r, uint32_t addr) {
    asm volatile("ldmatrix.sync.aligned.m8n8.x4.shared.b16 {%0,%1,%2,%3}, [%4];"
                 : "=r"(r[0]), "=r"(r[1]), "=r"(r[2]), "=r"(r[3]) : "r"(addr));
}
__device__ __forceinline__ void mma_bf16(float* c, const uint32_t* a,
                                         const uint32_t* b) {
    asm volatile(
        "mma.sync.aligned.m16n8k16.row.col.f32.bf16.bf16.f32 "
        "{%0,%1,%2,%3}, {%4,%5,%6,%7}, {%8,%9}, {%0,%1,%2,%3};"
        : "+f"(c[0]), "+f"(c[1]), "+f"(c[2]), "+f"(c[3])
        : "r"(a[0]), "r"(a[1]), "r"(a[2]), "r"(a[3]), "r"(b[0]), "r"(b[1]));
}
__device__ __forceinline__ void cp16(uint32_t saddr, const void* gptr) {
    asm volatile("cp.async.cg.shared.global [%0], [%1], 16;"
                 :: "r"(saddr), "l"(gptr));
}
__device__ __forceinline__ void cp_commit() {
    asm volatile("cp.async.commit_group;" ::: "memory");
}
template <int N>
__device__ __forceinline__ void cp_wait() {
    asm volatile("cp.async.wait_group %0;" :: "n"(N) : "memory");
}
// SW64 swizzle for 64B rows: chunk16 index ^= (row>>1)&3
__device__ __forceinline__ uint32_t swz64(uint32_t row, uint32_t cbyte) {
    return row * 64 + (cbyte ^ (((row >> 1) & 3) << 4));
}
__device__ __forceinline__ uint32_t pack2(__nv_bfloat16 a, __nv_bfloat16 b) {
    return (uint32_t)__bfloat16_as_ushort(a) | ((uint32_t)__bfloat16_as_ushort(b) << 16);
}

// gemm smem: 2 stages x 24KB (A hi 8K, A lo 8K, B hi 4K, B lo 4K) = 48KB static
#define ST_A_HI 0
#define ST_A_LO 8192
#define ST_B_HI 16384
#define ST_B_LO 20480
#define STAGE   24576
#define NCHUNK  8                      // 256 / 32

// ---------------- small kernels ---------------------------------------------
__global__ void zero_kernel() {
    int i = blockIdx.x * blockDim.x + threadIdx.x;
    if (i < NN * HEADS) { g_s1[i] = 0.f; g_s2[i] = 0.f; }
    if (i < NN) g_deg[i] = 0;
}

__global__ void detect_kernel(const int* __restrict__ edge_raw) {
    int lane = threadIdx.x & 31;
    int bad = 0;
    for (int i = lane; i < 2048; i += 32)
        if (edge_raw[2 * i + 1] != 0) bad = 1;
    unsigned m = __ballot_sync(0xffffffffu, bad);
    if (lane == 0 && blockIdx.x == 0) g_is64 = (m == 0);
}

__global__ void prep_b_kernel(const float* __restrict__ W) {
    int i = blockIdx.x * blockDim.x + threadIdx.x;
    if (i >= COLS * IN_F) return;
    float w = W[i];
    __nv_bfloat16 hi = __float2bfloat16(w);
    __nv_bfloat16 lo = __float2bfloat16(w - __bfloat162float(hi));
    g_Bhi[i] = hi;
    g_Blo[i] = lo;
}

__global__ void prep_a_kernel(const float* __restrict__ emb) {
    int i = blockIdx.x * blockDim.x + threadIdx.x;   // float4 granularity
    if (i >= M_PAD * (IN_F / 4)) return;
    int row = i >> 6;
    int c4  = i & 63;
    float4 v = make_float4(0.f, 0.f, 0.f, 0.f);
    if (row < NN && row != 0)
        v = *reinterpret_cast<const float4*>(emb + (size_t)row * IN_F + c4 * 4);
    __nv_bfloat16 h0 = __float2bfloat16(v.x), h1 = __float2bfloat16(v.y);
    __nv_bfloat16 h2 = __float2bfloat16(v.z), h3 = __float2bfloat16(v.w);
    __nv_bfloat16 l0 = __float2bfloat16(v.x - __bfloat162float(h0));
    __nv_bfloat16 l1 = __float2bfloat16(v.y - __bfloat162float(h1));
    __nv_bfloat16 l2 = __float2bfloat16(v.z - __bfloat162float(h2));
    __nv_bfloat16 l3 = __float2bfloat16(v.w - __bfloat162float(h3));
    size_t off = (size_t)row * IN_F + c4 * 4;
    *reinterpret_cast<uint2*>(g_Ahi + off) = make_uint2(pack2(h0, h1), pack2(h2, h3));
    *reinterpret_cast<uint2*>(g_Alo + off) = make_uint2(pack2(l0, l1), pack2(l2, l3));
}

// ---------------- split-bf16 HMMA GEMM, cp.async double-buffered -------------
// grid (391, 8): CTA = rows bm..bm+127, cols by*64..by*64+63.
// 8 warps in 4x2; warp tile 32x32. K in 8 chunks of 32, 2-stage pipeline.
__global__ __launch_bounds__(256, 2) void gemm_mma_kernel(
    const float* __restrict__ bias, const float* __restrict__ a_attn)
{
    __shared__ char smem[2 * STAGE];
    const uint32_t sb = smem_u32(smem);
    const int tid  = threadIdx.x;
    const int wid  = tid >> 5;
    const int lane = tid & 31;
    const int wm   = wid & 3;        // 0..3 (rows)
    const int wn   = wid >> 2;       // 0..1 (cols)
    const int bm   = blockIdx.x * 128;
    const int bn   = blockIdx.y * 64;
    const int h    = bn >> 7;        // head

    float acc[2][4][4];
#pragma unroll
    for (int i = 0; i < 2; i++)
#pragma unroll
        for (int j = 0; j < 4; j++)
#pragma unroll
            for (int r = 0; r < 4; r++) acc[i][j][r] = 0.f;

    // cp.async per-thread assignments (fixed per stage)
    const int a_row0 = tid >> 2;          // 0..63   (two rows per thread: +0,+64)
    const int a_c16  = tid & 3;           // 16B chunk 0..3
    const int b_row  = tid >> 2;          // 0..63
    // ldmatrix addressing
    const int arow = wm * 32 + (lane & 15);
    const uint32_t a_klane = (uint32_t)((lane >> 4) << 4);    // 0/16
    const uint32_t a_xor   = (uint32_t)(((arow >> 1) & 3) << 4);
    const int m4   = lane >> 3;
    const int brow = wn * 32 + ((m4 >> 1) << 3) + (lane & 7);
    const uint32_t b_klane = (uint32_t)((m4 & 1) << 4);
    const uint32_t b_xor   = (uint32_t)(((brow >> 1) & 3) << 4);

    auto load_stage = [&](int kc, int buf) {
        uint32_t s0 = sb + buf * STAGE;
        // A: 128 rows x 32 k, hi+lo (each thread: 2 rows x 1 chunk x 2 tensors)
#pragma unroll
        for (int l = 0; l < 2; l++) {
            int row = a_row0 + 64 * l;
            uint32_t so = swz64(row, a_c16 * 16);
            size_t gsrc = (size_t)(bm + row) * IN_F + kc * 32 + a_c16 * 8;
            cp16(s0 + ST_A_HI + so, g_Ahi + gsrc);
            cp16(s0 + ST_A_LO + so, g_Alo + gsrc);
        }
        // B: 64 rows x 32 k, hi+lo (each thread: 1 row x 1 chunk x 2 tensors)
        {
            uint32_t so = swz64(b_row, a_c16 * 16);
            size_t gsrc = (size_t)(bn + b_row) * IN_F + kc * 32 + a_c16 * 8;
            cp16(s0 + ST_B_HI + so, g_Bhi + gsrc);
            cp16(s0 + ST_B_LO + so, g_Blo + gsrc);
        }
        cp_commit();
    };

    load_stage(0, 0);

    for (int kc = 0; kc < NCHUNK; kc++) {
        if (kc + 1 < NCHUNK) load_stage(kc + 1, (kc + 1) & 1);
        if (kc + 1 < NCHUNK) cp_wait<1>(); else cp_wait<0>();
        __syncthreads();

        const uint32_t s0 = sb + (kc & 1) * STAGE;
        const uint32_t a_hi_b = s0 + ST_A_HI + arow * 64;
        const uint32_t a_lo_b = s0 + ST_A_LO + arow * 64;
        const uint32_t b_hi_b = s0 + ST_B_HI + brow * 64;
        const uint32_t b_lo_b = s0 + ST_B_LO + brow * 64;
#pragma unroll
        for (int ks = 0; ks < 2; ks++) {
            const uint32_t akb = ((uint32_t)(ks * 32) + a_klane) ^ a_xor;
            const uint32_t bkb = ((uint32_t)(ks * 32) + b_klane) ^ b_xor;
            uint32_t af[2][4], bh[2][4], bl[2][4];
#pragma unroll
            for (int i = 0; i < 2; i++)
                ldsm4(af[i], a_hi_b + i * 1024 + akb);
#pragma unroll
            for (int jp = 0; jp < 2; jp++)
                ldsm4(bh[jp], b_hi_b + jp * 1024 + bkb);
            // hi*hi
#pragma unroll
            for (int i = 0; i < 2; i++)
#pragma unroll
                for (int j = 0; j < 4; j++)
                    mma_bf16(acc[i][j], af[i], &bh[j >> 1][(j & 1) * 2]);
            // hi*lo
#pragma unroll
            for (int jp = 0; jp < 2; jp++)
                ldsm4(bl[jp], b_lo_b + jp * 1024 + bkb);
#pragma unroll
            for (int i = 0; i < 2; i++)
#pragma unroll
                for (int j = 0; j < 4; j++)
                    mma_bf16(acc[i][j], af[i], &bl[j >> 1][(j & 1) * 2]);
            // lo*hi (reuse af regs)
#pragma unroll
            for (int i = 0; i < 2; i++)
                ldsm4(af[i], a_lo_b + i * 1024 + akb);
#pragma unroll
            for (int i = 0; i < 2; i++)
#pragma unroll
                for (int j = 0; j < 4; j++)
                    mma_bf16(acc[i][j], af[i], &bh[j >> 1][(j & 1) * 2]);
        }
        __syncthreads();
    }

    // ---- epilogue: bias + X store + fused s1/s2 partials --------------------
    float* s1b = reinterpret_cast<float*>(smem);          // [128]
    float* s2b = reinterpret_cast<float*>(smem) + 128;    // [128]
    if (tid < 128) { s1b[tid] = 0.f; s2b[tid] = 0.f; }
    __syncthreads();

    const int chbase = bn - h * 128;                      // 0 or 64
    const float* a1 = a_attn + h * 2 * HID + chbase;
    const float* a2 = a1 + HID;
#pragma unroll
    for (int i = 0; i < 2; i++) {
        int r0 = wm * 32 + i * 16 + (lane >> 2);          // local row of (c0,c1)
        float p1a = 0.f, p2a = 0.f, p1b = 0.f, p2b = 0.f;
#pragma unroll
        for (int j = 0; j < 4; j++) {
            int c = wn * 32 + j * 8 + 2 * (lane & 3);     // local col (0..63)
            float b0 = bias[bn + c], b1 = bias[bn + c + 1];
            float x00 = acc[i][j][0] + b0, x01 = acc[i][j][1] + b1;
            float x10 = acc[i][j][2] + b0, x11 = acc[i][j][3] + b1;
            int gr0 = bm + r0, gr1 = gr0 + 8;
            if (gr0 < NN)
                *reinterpret_cast<float2*>(g_X + (size_t)gr0 * COLS + bn + c) =
                    make_float2(x00, x01);
            if (gr1 < NN)
                *reinterpret_cast<float2*>(g_X + (size_t)gr1 * COLS + bn + c) =
                    make_float2(x10, x11);
            float w10 = a1[c], w11 = a1[c + 1], w20 = a2[c], w21 = a2[c + 1];
            p1a = fmaf(x00, w10, fmaf(x01, w11, p1a));
            p2a = fmaf(x00, w20, fmaf(x01, w21, p2a));
            p1b = fmaf(x10, w10, fmaf(x11, w11, p1b));
            p2b = fmaf(x10, w20, fmaf(x11, w21, p2b));
        }
#pragma unroll
        for (int o = 1; o <= 2; o <<= 1) {
            p1a += __shfl_xor_sync(0xffffffffu, p1a, o);
            p2a += __shfl_xor_sync(0xffffffffu, p2a, o);
            p1b += __shfl_xor_sync(0xffffffffu, p1b, o);
            p2b += __shfl_xor_sync(0xffffffffu, p2b, o);
        }
        if ((lane & 3) == 0) {
            atomicAdd(&s1b[r0], p1a);
            atomicAdd(&s2b[r0], p2a);
            atomicAdd(&s1b[r0 + 8], p1b);
            atomicAdd(&s2b[r0 + 8], p2b);
        }
    }
    __syncthreads();
    if (tid < 128 && bm + tid < NN) {
        atomicAdd(&g_s1[(bm + tid) * 4 + h], s1b[tid]);
        atomicAdd(&g_s2[(bm + tid) * 4 + h], s2b[tid]);
    }
}

// ---------------- edge kernels ----------------------------------------------
__global__ void hist_kernel(const void* __restrict__ edge) {
    int e = blockIdx.x * blockDim.x + threadIdx.x;
    if (e >= EE) return;
    int src = load_edge(edge, e);
    atomicAdd(&g_deg[src], 1);
}

__global__ __launch_bounds__(256) void scan_kernel() {
    __shared__ int sums[256];
    const int t  = threadIdx.x;
    const int CH = (NN + 255) / 256;
    int beg = t * CH, end = min(beg + CH, NN);
    int s = 0;
    for (int i = beg; i < end; i++) s += g_deg[i];
    sums[t] = s;
    __syncthreads();
    if (t == 0) {
        int run = 0;
        for (int i = 0; i < 256; i++) { int v = sums[i]; sums[i] = run; run += v; }
    }
    __syncthreads();
    int run = sums[t];
    for (int i = beg; i < end; i++) {
        g_rowptr[i] = run;
        g_cursor[i] = run;
        run += g_deg[i];
    }
    if (t == 0) g_rowptr[NN] = EE;
}

__global__ __launch_bounds__(256) void score_scatter_kernel(const void* __restrict__ edge) {
    int e = blockIdx.x * blockDim.x + threadIdx.x;
    if (e >= EE) return;
    int src = load_edge(edge, e);
    int dst = load_edge(edge, (long long)EE + e);
    float4 v1 = *reinterpret_cast<const float4*>(g_s1 + src * 4);
    float4 v2 = *reinterpret_cast<const float4*>(g_s2 + dst * 4);
    float4 sc;
    {
        float s0 = v1.x + v2.x, s1 = v1.y + v2.y, s2 = v1.z + v2.z, s3 = v1.w + v2.w;
        s0 = (s0 >= 0.f ? s0 : ALPHA_L * s0) * INV_SCALE;
        s1 = (s1 >= 0.f ? s1 : ALPHA_L * s1) * INV_SCALE;
        s2 = (s2 >= 0.f ? s2 : ALPHA_L * s2) * INV_SCALE;
        s3 = (s3 >= 0.f ? s3 : ALPHA_L * s3) * INV_SCALE;
        sc = make_float4(expf(s0), expf(s1), expf(s2), expf(s3));
    }
    int pos = atomicAdd(&g_cursor[src], 1);
    g_dsts[pos] = dst;
    g_es[pos]   = sc;
}

// One block (128 thr) per node: gather-aggregate + LayerNorm + ELU.
// Software-pipelined: next edge's meta loads overlap current gathers.
__global__ __launch_bounds__(128) void agg_ln_kernel(
    const float* __restrict__ gain, const float* __restrict__ beta,
    float* __restrict__ out)
{
    const int n = blockIdx.x;
    const int t = threadIdx.x;
    const int beg = g_rowptr[n], end = g_rowptr[n + 1];

    float a0 = 0.f, a1 = 0.f, a2 = 0.f, a3 = 0.f;
    float r0 = 0.f, r1 = 0.f, r2 = 0.f, r3 = 0.f;
    int d = 0; float4 e = make_float4(0.f, 0.f, 0.f, 0.f);
    if (beg < end) { d = g_dsts[beg]; e = g_es[beg]; }
    for (int i = beg; i < end; i++) {
        int dn = 0; float4 en;
        if (i + 1 < end) { dn = g_dsts[i + 1]; en = g_es[i + 1]; }
        else             { en = make_float4(0.f, 0.f, 0.f, 0.f); }
        const float* xr = g_X + (size_t)d * COLS;
        a0 = fmaf(e.x, xr[t],            a0);
        a1 = fmaf(e.y, xr[HID + t],      a1);
        a2 = fmaf(e.z, xr[2 * HID + t],  a2);
        a3 = fmaf(e.w, xr[3 * HID + t],  a3);
        r0 += e.x; r1 += e.y; r2 += e.z; r3 += e.w;
        d = dn; e = en;
    }
    float h0 = a0 / (r0 == 0.f ? 1.f : r0);
    float h1 = a1 / (r1 == 0.f ? 1.f : r1);
    float h2 = a2 / (r2 == 0.f ? 1.f : r2);
    float h3 = a3 / (r3 == 0.f ? 1.f : r3);

    float s  = h0 + h1 + h2 + h3;
    float ss = h0 * h0 + h1 * h1 + h2 * h2 + h3 * h3;
#pragma unroll
    for (int o = 16; o; o >>= 1) {
        s  += __shfl_xor_sync(0xffffffffu, s, o);
        ss += __shfl_xor_sync(0xffffffffu, ss, o);
    }
    __shared__ float rs[4], rss[4];
    int w = t >> 5;
    if ((t & 31) == 0) { rs[w] = s; rss[w] = ss; }
    __syncthreads();
    s  = rs[0] + rs[1] + rs[2] + rs[3];
    ss = rss[0] + rss[1] + rss[2] + rss[3];

    float mean = s * (1.f / 512.f);
    float var  = fmaxf((ss - 512.f * mean * mean) * (1.f / 511.f), 0.f);
    float inv  = 1.f / (sqrtf(var) + LN_EPS);

    float* orow = out + (size_t)n * COLS;
    float hv[4] = {h0, h1, h2, h3};
#pragma unroll
    for (int h = 0; h < 4; h++) {
        int c = h * HID + t;
        float v = gain[c] * (hv[h] - mean) * inv + beta[c];
        orow[c] = v > 0.f ? v : expm1f(v);
    }
}

// ---------------- launch -----------------------------------------------------
extern "C" void kernel_launch(void* const* d_in, const int* in_sizes, int n_in,
                              void* d_out, int out_size)
{
    (void)in_sizes; (void)n_in; (void)out_size;
    const void*  edge   = d_in[1];
    const float* emb    = (const float*)d_in[2];
    const float* W      = (const float*)d_in[3];
    const float* bias   = (const float*)d_in[4];
    const float* a_attn = (const float*)d_in[5];
    const float* gain   = (const float*)d_in[6];
    const float* beta   = (const float*)d_in[7];
    float* out = (float*)d_out;

    detect_kernel<<<1, 32>>>((const int*)edge);
    zero_kernel<<<(NN * HEADS + 255) / 256, 256>>>();
    prep_b_kernel<<<(COLS * IN_F + 255) / 256, 256>>>(W);
    prep_a_kernel<<<(M_PAD * (IN_F / 4) + 255) / 256, 256>>>(emb);

    dim3 gg(M_TILES, 8);
    gemm_mma_kernel<<<gg, 256>>>(bias, a_attn);

    hist_kernel<<<(EE + 255) / 256, 256>>>(edge);
    scan_kernel<<<1, 256>>>();
    score_scatter_kernel<<<(EE + 255) / 256, 256>>>(edge);

    agg_ln_kernel<<<NN, 128>>>(gain, beta, out);
}